// round 11
// baseline (speedup 1.0000x reference)
#include <cuda_runtime.h>
#include <cuda_bf16.h>
#include <cuda_fp8.h>
#include <cstdint>
#include <math.h>

typedef __nv_bfloat16 bf16;

#define Bz 32
#define Dz 2048
#define Gz 8192
#define Vz 10000
#define Tz 20
#define Xz 36

#define WSCALE 32.f
#define HSCALE 8.f
#define UNSCALE (1.f / 256.f)

// ---------------- device scratch (allocation-free rule: __device__ globals) ----------------
__device__ __align__(256) uint8_t g_f8Ah [Gz*Dz];   // e4m3: Wih_a[:,0:2048]*32
__device__ __align__(256) uint8_t g_f8Ahh[Gz*Dz];   // e4m3: Whh_a*32
__device__ __align__(256) uint8_t g_f8Lh [Gz*Dz];   // e4m3: Wih_l[:,0:2048]*32
__device__ __align__(256) uint8_t g_f8Lhh[Gz*Dz];   // e4m3: Whh_l*32
__device__ __align__(256) bf16 g_bAv [Gz*Dz];       // Wih_a[:,2048:4096] (v_bar block)
__device__ __align__(256) bf16 g_bAe [Gz*Dz];       // Wih_a[:,4096:6144] (emb block)
__device__ __align__(256) bf16 g_bLv [Gz*Dz];       // Wih_l[:,2048:4096] (v_hat block)
__device__ __align__(256) bf16 g_bFC [Vz*Dz];       // Wfc
__device__ __align__(256) bf16 g_embsB[Bz*Tz*Dz];   // [t*32+b, k]
__device__ __align__(256) bf16 g_vbarB[Bz*Dz];
__device__ __align__(256) bf16 g_vhatB[Bz*Dz];
__device__ __align__(256) uint8_t g_h8a[Bz*Dz];     // e4m3: h_a*8
__device__ __align__(256) uint8_t g_h8l[Bz*Dz];     // e4m3: h_l*8
__device__ __align__(256) bf16 g_hlAll[Tz*Bz*Dz];   // rows t*32+b (bf16 for logits GEMM)
__device__ __align__(256) float g_caF[Bz*Dz];
__device__ __align__(256) float g_clF[Bz*Dz];
__device__ __align__(256) float g_zF[5*Bz*Gz];      // 5 partial-z slabs
__device__ __align__(256) float g_prevAF[Bz*Gz];
__device__ __align__(256) float g_preLF[Bz*Gz];
__device__ __align__(256) float g_preAF[Bz*Tz*Gz];
__device__ unsigned g_cnt[2 * Tz];                   // per-(step,phase) job counters

struct JobSet8 {
    const uint8_t* A[3];
    const uint8_t* W[3];
    float*         Z[3];
    int            kOff[3];
};

__device__ __forceinline__ uint32_t smem_u32(const void* p) {
    return (uint32_t)__cvta_generic_to_shared(p);
}

// ---------------- fp32 -> bf16 strided column-block conversion (4 elems/thread) ----------
__global__ void k_conv(const float* __restrict__ src, int stride, int off,
                       bf16* __restrict__ dst, int total4) {
    int i = blockIdx.x * 256 + threadIdx.x;
    if (i >= total4) return;
    int base = i << 2;
    int n = base >> 11, k = base & 2047;
    const float* p = src + (size_t)n * stride + off + k;
    bf16* q = dst + base;
    q[0] = __float2bfloat16(p[0]);
    q[1] = __float2bfloat16(p[1]);
    q[2] = __float2bfloat16(p[2]);
    q[3] = __float2bfloat16(p[3]);
}

// ---------------- fp32 -> e4m3 (x WSCALE) conversion, packed 4B store ----------------
__global__ void k_conv8(const float* __restrict__ src, int stride, int off,
                        uint8_t* __restrict__ dst, int total4) {
    int i = blockIdx.x * 256 + threadIdx.x;
    if (i >= total4) return;
    int base = i << 2;
    int n = base >> 11, k = base & 2047;
    const float* p = src + (size_t)n * stride + off + k;
    uint32_t b0 = __nv_cvt_float_to_fp8(p[0] * WSCALE, __NV_SATFINITE, __NV_E4M3);
    uint32_t b1 = __nv_cvt_float_to_fp8(p[1] * WSCALE, __NV_SATFINITE, __NV_E4M3);
    uint32_t b2 = __nv_cvt_float_to_fp8(p[2] * WSCALE, __NV_SATFINITE, __NV_E4M3);
    uint32_t b3 = __nv_cvt_float_to_fp8(p[3] * WSCALE, __NV_SATFINITE, __NV_E4M3);
    *(uint32_t*)(dst + base) = b0 | (b1 << 8) | (b2 << 16) | (b3 << 24);
}

// ---------------- features reduction ----------------
__global__ void k_feat(const float* __restrict__ f) {
    int i = blockIdx.x * 256 + threadIdx.x;
    if (i >= Bz * Dz) return;
    int b = i >> 11, k = i & 2047;
    const float* p = f + (size_t)b * Xz * Dz + k;
    float s = 0.f;
#pragma unroll
    for (int x = 0; x < Xz; x++) s += p[x * Dz];
    g_vbarB[i] = __float2bfloat16(s * (1.f / 36.f));
    g_vhatB[i] = __float2bfloat16(s);
}

// ---------------- embedding gather, t-major rows ----------------
__global__ void k_embs(const float* __restrict__ emb, const int* __restrict__ cap) {
    int i = blockIdx.x * 256 + threadIdx.x;
    if (i >= Bz * Tz * Dz) return;
    int k = i & 2047, r = i >> 11;
    int t = r >> 5, b = r & 31;
    int tok = cap[b * Tz + t];
    g_embsB[i] = __float2bfloat16(emb[(size_t)tok * Dz + k]);
}

#define STAGES 4

// ---------------- generic bf16 tensor-core GEMM (precompute + logits) ----------------
__global__ void __launch_bounds__(128)
k_gemm(const bf16* __restrict__ A1, const bf16* __restrict__ W1, int K1,
       const bf16* __restrict__ A2, const bf16* __restrict__ W2, int K2,
       const float* __restrict__ P, int ldP, int pLocal,
       const float* __restrict__ bias1, const float* __restrict__ bias2,
       float* __restrict__ Z, int ldZ, int N, int remapBT)
{
    __shared__ __align__(128) bf16 sA[STAGES][32 * 72];
    __shared__ __align__(128) bf16 sW[STAGES][32 * 72];

    const int tid   = threadIdx.x;
    const int lane  = tid & 31;
    const int warp  = tid >> 5;
    const int nBlk  = blockIdx.x * 32;
    const int mBase = blockIdx.y * 32;
    const int s1      = K1 >> 6;
    const int nStages = (K1 + K2) >> 6;

    const int lr0 = tid >> 3;
    const int lc  = (tid & 7) * 8;

    auto loadStage = [&](int s, int buf) {
        int kg = s << 6;
        const bf16* Ap; const bf16* Wp; int K; int ko;
        if (s < s1) { Ap = A1; Wp = W1; K = K1; ko = kg; }
        else        { Ap = A2; Wp = W2; K = K2; ko = kg - (s1 << 6); }
#pragma unroll
        for (int half = 0; half < 2; half++) {
            int row = lr0 + half * 16;
            uint32_t da = smem_u32(&sA[buf][row * 72 + lc]);
            const bf16* ga = Ap + (size_t)(mBase + row) * K + ko + lc;
            asm volatile("cp.async.cg.shared.global [%0], [%1], 16;\n" :: "r"(da), "l"(ga));
            int wr = nBlk + row;
            uint32_t dw = smem_u32(&sW[buf][row * 72 + lc]);
            const bf16* gw = Wp + (size_t)(wr < N ? wr : 0) * K + ko + lc;
            int sz = (wr < N) ? 16 : 0;
            asm volatile("cp.async.cg.shared.global [%0], [%1], 16, %2;\n"
                         :: "r"(dw), "l"(gw), "r"(sz));
        }
    };

#pragma unroll
    for (int s = 0; s < STAGES - 1; s++) {
        if (s < nStages) loadStage(s, s);
        asm volatile("cp.async.commit_group;\n");
    }

    float d0[4] = {0, 0, 0, 0}, d1[4] = {0, 0, 0, 0};
    const int aR = lane & 15;
    const int aC = (lane >> 4) * 8;
    const int bR = warp * 8 + (lane & 7);
    const int bC = ((lane >> 3) & 1) * 8;

    for (int s = 0; s < nStages; s++) {
        if (s + STAGES - 1 < nStages) loadStage(s + STAGES - 1, (s + STAGES - 1) % STAGES);
        asm volatile("cp.async.commit_group;\n");
        asm volatile("cp.async.wait_group %0;\n" :: "n"(STAGES - 1));
        __syncthreads();
        const bf16* pa = sA[s % STAGES];
        const bf16* pw = sW[s % STAGES];
#pragma unroll
        for (int kk = 0; kk < 64; kk += 16) {
            uint32_t a0[4], a1[4], bb[2];
            uint32_t ad0 = smem_u32(&pa[aR * 72 + kk + aC]);
            uint32_t ad1 = smem_u32(&pa[(aR + 16) * 72 + kk + aC]);
            uint32_t adb = smem_u32(&pw[bR * 72 + kk + bC]);
            asm volatile("ldmatrix.sync.aligned.m8n8.x4.shared.b16 {%0,%1,%2,%3}, [%4];\n"
                : "=r"(a0[0]), "=r"(a0[1]), "=r"(a0[2]), "=r"(a0[3]) : "r"(ad0));
            asm volatile("ldmatrix.sync.aligned.m8n8.x4.shared.b16 {%0,%1,%2,%3}, [%4];\n"
                : "=r"(a1[0]), "=r"(a1[1]), "=r"(a1[2]), "=r"(a1[3]) : "r"(ad1));
            asm volatile("ldmatrix.sync.aligned.m8n8.x2.shared.b16 {%0,%1}, [%2];\n"
                : "=r"(bb[0]), "=r"(bb[1]) : "r"(adb));
            asm volatile("mma.sync.aligned.m16n8k16.row.col.f32.bf16.bf16.f32 "
                "{%0,%1,%2,%3}, {%4,%5,%6,%7}, {%8,%9}, {%0,%1,%2,%3};\n"
                : "+f"(d0[0]), "+f"(d0[1]), "+f"(d0[2]), "+f"(d0[3])
                : "r"(a0[0]), "r"(a0[1]), "r"(a0[2]), "r"(a0[3]), "r"(bb[0]), "r"(bb[1]));
            asm volatile("mma.sync.aligned.m16n8k16.row.col.f32.bf16.bf16.f32 "
                "{%0,%1,%2,%3}, {%4,%5,%6,%7}, {%8,%9}, {%0,%1,%2,%3};\n"
                : "+f"(d1[0]), "+f"(d1[1]), "+f"(d1[2]), "+f"(d1[3])
                : "r"(a1[0]), "r"(a1[1]), "r"(a1[2]), "r"(a1[3]), "r"(bb[0]), "r"(bb[1]));
        }
        __syncthreads();
    }

    const int g = lane >> 2, tg = lane & 3;
    const int ncol = nBlk + warp * 8 + tg * 2;
#pragma unroll
    for (int mt = 0; mt < 2; mt++) {
        const float* dd = mt ? d1 : d0;
#pragma unroll
        for (int rr = 0; rr < 2; rr++) {
            int m = mt * 16 + rr * 8 + g;
            int row = mBase + m;
            int prow = pLocal ? (row & 31) : row;
            int orow = remapBT ? ((row & 31) * Tz + (row >> 5)) : row;
#pragma unroll
            for (int cc = 0; cc < 2; cc++) {
                int col = ncol + cc;
                if (col < N) {
                    float v = dd[rr * 2 + cc];
                    if (P)     v += P[(size_t)prow * ldP + col];
                    if (bias1) v += bias1[col];
                    if (bias2) v += bias2[col];
                    Z[(size_t)orow * ldZ + col] = v;
                }
            }
        }
    }
}

// ---------------- fp8 GEMM tile (device fn): one 32x32 N-tile, KTILE=128 e4m3 ----------
__device__ __forceinline__ void gemm_tile8(
    const uint8_t* __restrict__ A, const uint8_t* __restrict__ W,
    float* __restrict__ Z, int kOff, int kLen, int nBlk,
    uint8_t (&sA)[STAGES][32 * 144], uint8_t (&sW)[STAGES][32 * 144])
{
    const int tid  = threadIdx.x;
    const int lane = tid & 31;
    const int warp = tid >> 5;
    const int nStages = kLen >> 7;

    const int lr0 = tid >> 3;
    const int lc  = (tid & 7) * 16;

    auto loadStage = [&](int s, int buf) {
        int ko = (s << 7) + kOff;
#pragma unroll
        for (int half = 0; half < 2; half++) {
            int row = lr0 + half * 16;
            uint32_t da = smem_u32(&sA[buf][row * 144 + lc]);
            const uint8_t* ga = A + (size_t)row * Dz + ko + lc;
            asm volatile("cp.async.cg.shared.global [%0], [%1], 16;\n" :: "r"(da), "l"(ga));
            uint32_t dw = smem_u32(&sW[buf][row * 144 + lc]);
            const uint8_t* gw = W + (size_t)(nBlk + row) * Dz + ko + lc;
            asm volatile("cp.async.cg.shared.global [%0], [%1], 16;\n" :: "r"(dw), "l"(gw));
        }
    };

#pragma unroll
    for (int s = 0; s < STAGES - 1; s++) {
        if (s < nStages) loadStage(s, s);
        asm volatile("cp.async.commit_group;\n");
    }

    float d0[4] = {0, 0, 0, 0}, d1[4] = {0, 0, 0, 0};
    const int aR  = lane & 15;
    const int aCB = (lane >> 4) * 16;
    const int bR  = warp * 8 + (lane & 7);
    const int bCB = ((lane >> 3) & 1) * 16;

    for (int s = 0; s < nStages; s++) {
        if (s + STAGES - 1 < nStages) loadStage(s + STAGES - 1, (s + STAGES - 1) % STAGES);
        asm volatile("cp.async.commit_group;\n");
        asm volatile("cp.async.wait_group %0;\n" :: "n"(STAGES - 1));
        __syncthreads();
        const uint8_t* pa = sA[s % STAGES];
        const uint8_t* pw = sW[s % STAGES];
#pragma unroll
        for (int kk = 0; kk < 128; kk += 32) {
            uint32_t a0[4], a1[4], bb[2];
            uint32_t ad0 = smem_u32(&pa[aR * 144 + kk + aCB]);
            uint32_t ad1 = smem_u32(&pa[(aR + 16) * 144 + kk + aCB]);
            uint32_t adb = smem_u32(&pw[bR * 144 + kk + bCB]);
            asm volatile("ldmatrix.sync.aligned.m8n8.x4.shared.b16 {%0,%1,%2,%3}, [%4];\n"
                : "=r"(a0[0]), "=r"(a0[1]), "=r"(a0[2]), "=r"(a0[3]) : "r"(ad0));
            asm volatile("ldmatrix.sync.aligned.m8n8.x4.shared.b16 {%0,%1,%2,%3}, [%4];\n"
                : "=r"(a1[0]), "=r"(a1[1]), "=r"(a1[2]), "=r"(a1[3]) : "r"(ad1));
            asm volatile("ldmatrix.sync.aligned.m8n8.x2.shared.b16 {%0,%1}, [%2];\n"
                : "=r"(bb[0]), "=r"(bb[1]) : "r"(adb));
            asm volatile("mma.sync.aligned.m16n8k32.row.col.f32.e4m3.e4m3.f32 "
                "{%0,%1,%2,%3}, {%4,%5,%6,%7}, {%8,%9}, {%0,%1,%2,%3};\n"
                : "+f"(d0[0]), "+f"(d0[1]), "+f"(d0[2]), "+f"(d0[3])
                : "r"(a0[0]), "r"(a0[1]), "r"(a0[2]), "r"(a0[3]), "r"(bb[0]), "r"(bb[1]));
            asm volatile("mma.sync.aligned.m16n8k32.row.col.f32.e4m3.e4m3.f32 "
                "{%0,%1,%2,%3}, {%4,%5,%6,%7}, {%8,%9}, {%0,%1,%2,%3};\n"
                : "+f"(d1[0]), "+f"(d1[1]), "+f"(d1[2]), "+f"(d1[3])
                : "r"(a1[0]), "r"(a1[1]), "r"(a1[2]), "r"(a1[3]), "r"(bb[0]), "r"(bb[1]));
        }
        __syncthreads();
    }

    const int g = lane >> 2, tg = lane & 3;
    const int ncol = nBlk + warp * 8 + tg * 2;
#pragma unroll
    for (int mt = 0; mt < 2; mt++) {
        const float* dd = mt ? d1 : d0;
#pragma unroll
        for (int rr = 0; rr < 2; rr++) {
            int m = mt * 16 + rr * 8 + g;
#pragma unroll
            for (int cc = 0; cc < 2; cc++) {
                int col = ncol + cc;
                Z[(size_t)m * Gz + col] = dd[rr * 2 + cc] * UNSCALE;
            }
        }
    }
}

#define CELLBLOCKS 64
#define CELLSPAN   (Bz * Dz / CELLBLOCKS)   // 1024 elems per cell block

// ---------------- fused step kernel: GEMM tiles + producer-counter cell epilogue --------
// Each block does one 32x32 GEMM tile (job j: m = j>>8 selects (A,W,Z,kOff), n = j&255).
// After writing z it releases via atomicAdd(cnt). Blocks j < CELLBLOCKS then spin until
// all nJobs are done and run their 1024-element slice of the LSTM cell.
__global__ void __launch_bounds__(128)
k_stepF(JobSet8 js, int kLen, int nJobs, unsigned* cnt,
        const float* __restrict__ cz0, const float* __restrict__ cz1,
        const float* __restrict__ cz2, const float* __restrict__ pre,
        float* __restrict__ c, uint8_t* __restrict__ h8, bf16* __restrict__ hCopy)
{
    __shared__ __align__(128) uint8_t sA[STAGES][32 * 144];
    __shared__ __align__(128) uint8_t sW[STAGES][32 * 144];

    const int j = blockIdx.x;
    const int m = j >> 8, n = j & 255;
    gemm_tile8(js.A[m], js.W[m], js.Z[m], js.kOff[m], kLen, n * 32, sA, sW);

    // release: all block stores visible, then count this job done
    __threadfence();
    __syncthreads();
    if (threadIdx.x == 0) atomicAdd(cnt, 1u);

    if (j >= CELLBLOCKS) return;

    // designated cell blocks: wait for all GEMM jobs, then cell slice
    if (threadIdx.x == 0) {
        while (*(volatile unsigned*)cnt < (unsigned)nJobs) __nanosleep(32);
    }
    __syncthreads();
    __threadfence();

    const int lo = j * CELLSPAN;
    for (int i = lo + threadIdx.x; i < lo + CELLSPAN; i += 128) {
        int b = i >> 11, d = i & 2047;
        size_t o = (size_t)b * Gz + d;
        float ii = __ldcg(cz0 + o)          + __ldcg(cz1 + o)          + pre[o];
        float ff = __ldcg(cz0 + o + Dz)     + __ldcg(cz1 + o + Dz)     + pre[o + Dz];
        float gg = __ldcg(cz0 + o + 2 * Dz) + __ldcg(cz1 + o + 2 * Dz) + pre[o + 2 * Dz];
        float oo = __ldcg(cz0 + o + 3 * Dz) + __ldcg(cz1 + o + 3 * Dz) + pre[o + 3 * Dz];
        if (cz2) {
            ii += __ldcg(cz2 + o);
            ff += __ldcg(cz2 + o + Dz);
            gg += __ldcg(cz2 + o + 2 * Dz);
            oo += __ldcg(cz2 + o + 3 * Dz);
        }
        float si = 1.f / (1.f + expf(-ii));
        float sf = 1.f / (1.f + expf(-ff));
        float so = 1.f / (1.f + expf(-oo));
        float tg = tanhf(gg);
        float cn = sf * c[i] + si * tg;
        c[i] = cn;
        float hv = so * tanhf(cn);
        h8[i] = __nv_cvt_float_to_fp8(hv * HSCALE, __NV_SATFINITE, __NV_E4M3);
        if (hCopy) hCopy[i] = __float2bfloat16(hv);
    }
}

// ---------------- in-place log_softmax over V per (b,t) row ----------------
__global__ void k_lsm(float* __restrict__ out) {
    __shared__ float red[8];
    int r = blockIdx.x;
    float* p = out + (size_t)r * Vz;
    int tid = threadIdx.x;
    float m = -1e30f;
    for (int i = tid; i < Vz; i += 256) m = fmaxf(m, p[i]);
#pragma unroll
    for (int o = 16; o > 0; o >>= 1) m = fmaxf(m, __shfl_xor_sync(0xffffffffu, m, o));
    if ((tid & 31) == 0) red[tid >> 5] = m;
    __syncthreads();
    if (tid == 0) {
        float mm = red[0];
        for (int j = 1; j < 8; j++) mm = fmaxf(mm, red[j]);
        red[0] = mm;
    }
    __syncthreads();
    m = red[0];
    __syncthreads();
    float s = 0.f;
    for (int i = tid; i < Vz; i += 256) s += expf(p[i] - m);
#pragma unroll
    for (int o = 16; o > 0; o >>= 1) s += __shfl_xor_sync(0xffffffffu, s, o);
    if ((tid & 31) == 0) red[tid >> 5] = s;
    __syncthreads();
    if (tid == 0) {
        float ss = 0.f;
        for (int j = 0; j < 8; j++) ss += red[j];
        red[0] = ss;
    }
    __syncthreads();
    float lse = m + logf(red[0]);
    for (int i = tid; i < Vz; i += 256) p[i] -= lse;
}

// ---------------- host ----------------
extern "C" void kernel_launch(void* const* d_in, const int* in_sizes, int n_in,
                              void* d_out, int out_size) {
    const float* features = (const float*)d_in[0];
    const int*   caption  = (const int*)  d_in[1];
    const float* emb      = (const float*)d_in[2];
    const float* Wih_a    = (const float*)d_in[3];
    const float* Whh_a    = (const float*)d_in[4];
    const float* bih_a    = (const float*)d_in[5];
    const float* bhh_a    = (const float*)d_in[6];
    const float* Wih_l    = (const float*)d_in[7];
    const float* Whh_l    = (const float*)d_in[8];
    const float* bih_l    = (const float*)d_in[9];
    const float* bhh_l    = (const float*)d_in[10];
    const float* Wfc      = (const float*)d_in[17];
    const float* bfc      = (const float*)d_in[18];
    float* out = (float*)d_out;

    uint8_t *f8Ah, *f8Ahh, *f8Lh, *f8Lhh, *h8a, *h8l;
    bf16 *bAv, *bAe, *bLv, *bFC, *embsB, *vbarB, *vhatB, *hlAll;
    float *ca, *cl, *zz, *prevA, *preL, *preA;
    unsigned* cntp;
    cudaGetSymbolAddress((void**)&f8Ah,  g_f8Ah);
    cudaGetSymbolAddress((void**)&f8Ahh, g_f8Ahh);
    cudaGetSymbolAddress((void**)&f8Lh,  g_f8Lh);
    cudaGetSymbolAddress((void**)&f8Lhh, g_f8Lhh);
    cudaGetSymbolAddress((void**)&h8a,   g_h8a);
    cudaGetSymbolAddress((void**)&h8l,   g_h8l);
    cudaGetSymbolAddress((void**)&bAv,   g_bAv);
    cudaGetSymbolAddress((void**)&bAe,   g_bAe);
    cudaGetSymbolAddress((void**)&bLv,   g_bLv);
    cudaGetSymbolAddress((void**)&bFC,   g_bFC);
    cudaGetSymbolAddress((void**)&embsB, g_embsB);
    cudaGetSymbolAddress((void**)&vbarB, g_vbarB);
    cudaGetSymbolAddress((void**)&vhatB, g_vhatB);
    cudaGetSymbolAddress((void**)&hlAll, g_hlAll);
    cudaGetSymbolAddress((void**)&ca,    g_caF);
    cudaGetSymbolAddress((void**)&cl,    g_clF);
    cudaGetSymbolAddress((void**)&zz,    g_zF);
    cudaGetSymbolAddress((void**)&prevA, g_prevAF);
    cudaGetSymbolAddress((void**)&preL,  g_preLF);
    cudaGetSymbolAddress((void**)&preA,  g_preAF);
    cudaGetSymbolAddress((void**)&cntp,  g_cnt);

    const size_t SLAB = (size_t)Bz * Gz;

    // init recurrent state + job counters (fresh per graph replay)
    cudaMemsetAsync(ca,  0, (size_t)Bz * Dz * sizeof(float));
    cudaMemsetAsync(cl,  0, (size_t)Bz * Dz * sizeof(float));
    cudaMemsetAsync(h8a, 0, (size_t)Bz * Dz);
    cudaMemsetAsync(h8l, 0, (size_t)Bz * Dz);
    cudaMemsetAsync(cntp, 0, 2 * Tz * sizeof(unsigned));

    // one-shot precompute
    k_feat<<<(Bz * Dz + 255) / 256, 256>>>(features);
    k_embs<<<(Bz * Tz * Dz + 255) / 256, 256>>>(emb, caption);

    const int cv4 = Gz * Dz / 4;
    k_conv8<<<cv4 / 256, 256>>>(Wih_a, 3 * Dz, 0,  f8Ah,  cv4);
    k_conv8<<<cv4 / 256, 256>>>(Whh_a, Dz,     0,  f8Ahh, cv4);
    k_conv8<<<cv4 / 256, 256>>>(Wih_l, 2 * Dz, 0,  f8Lh,  cv4);
    k_conv8<<<cv4 / 256, 256>>>(Whh_l, Dz,     0,  f8Lhh, cv4);
    k_conv<<<cv4 / 256, 256>>>(Wih_a, 3 * Dz, Dz,     bAv, cv4);
    k_conv<<<cv4 / 256, 256>>>(Wih_a, 3 * Dz, 2 * Dz, bAe, cv4);
    k_conv<<<cv4 / 256, 256>>>(Wih_l, 2 * Dz, Dz,     bLv, cv4);
    k_conv<<<(Vz * Dz / 4 + 255) / 256, 256>>>(Wfc, Dz, 0, bFC, Vz * Dz / 4);

    dim3 blk(128);
    // prevA[b,:] = v_bar @ bAv^T + bih_a + bhh_a
    k_gemm<<<dim3(Gz / 32, 1), blk>>>(vbarB, bAv, Dz, vbarB, bAv, 0,
                                      nullptr, 0, 0, bih_a, bhh_a, prevA, Gz, Gz, 0);
    // preA[t*32+b,:] = prevA[b,:] + e_{b,t} @ bAe^T
    k_gemm<<<dim3(Gz / 32, Tz), blk>>>(embsB, bAe, Dz, embsB, bAe, 0,
                                       prevA, Gz, 1, nullptr, nullptr, preA, Gz, Gz, 0);
    // preL[b,:] = v_hat @ bLv^T + bih_l + bhh_l
    k_gemm<<<dim3(Gz / 32, 1), blk>>>(vhatB, bLv, Dz, vhatB, bLv, 0,
                                      nullptr, 0, 0, bih_l, bhh_l, preL, Gz, Gz, 0);

    for (int t = 0; t < Tz; t++) {
        // X launch: 768 jobs {hl@Ah->slab0, ha@Ahh->slab1, hl@Lhh->slab2} + fused cellA
        JobSet8 jx;
        jx.A[0] = h8l;  jx.W[0] = f8Ah;   jx.Z[0] = zz;             jx.kOff[0] = 0;
        jx.A[1] = h8a;  jx.W[1] = f8Ahh;  jx.Z[1] = zz + SLAB;      jx.kOff[1] = 0;
        jx.A[2] = h8l;  jx.W[2] = f8Lhh;  jx.Z[2] = zz + 2 * SLAB;  jx.kOff[2] = 0;
        k_stepF<<<768, blk>>>(jx, Dz, 768, cntp + 2 * t,
                              zz, zz + SLAB, nullptr, preA + (size_t)t * SLAB,
                              ca, h8a, nullptr);
        // Y launch: 512 jobs {ha@Lh K-halves -> slab3, slab4} + fused cellL
        JobSet8 jy;
        jy.A[0] = h8a;  jy.W[0] = f8Lh;  jy.Z[0] = zz + 3 * SLAB;  jy.kOff[0] = 0;
        jy.A[1] = h8a;  jy.W[1] = f8Lh;  jy.Z[1] = zz + 4 * SLAB;  jy.kOff[1] = 1024;
        jy.A[2] = h8a;  jy.W[2] = f8Lh;  jy.Z[2] = zz + 4 * SLAB;  jy.kOff[2] = 1024;
        k_stepF<<<512, blk>>>(jy, 1024, 512, cntp + 2 * t + 1,
                              zz + 2 * SLAB, zz + 3 * SLAB, zz + 4 * SLAB, preL,
                              cl, h8l, hlAll + (size_t)t * Bz * Dz);
    }

    // batched logits: rows r=t*32+b of hlAll @ Wfc^T + bfc -> out[b][t][:]
    k_gemm<<<dim3((Vz + 31) / 32, Tz), blk>>>(hlAll, bFC, Dz, hlAll, bFC, 0,
                                              nullptr, 0, 0, bfc, nullptr,
                                              out, Vz, Vz, 1);
    k_lsm<<<Bz * Tz, 256>>>(out);
}

// round 13
// speedup vs baseline: 1.2329x; 1.2329x over previous
#include <cuda_runtime.h>
#include <cuda_bf16.h>
#include <cuda_fp8.h>
#include <cstdint>
#include <math.h>

typedef __nv_bfloat16 bf16;

#define Bz 32
#define Dz 2048
#define Gz 8192
#define Vz 10000
#define Tz 20
#define Xz 36

#define WSCALE 32.f
#define HSCALE 8.f
#define UNSCALE (1.f / 256.f)

// ---------------- device scratch (allocation-free rule: __device__ globals) ----------------
__device__ __align__(256) uint8_t g_f8Ah [Gz*Dz];   // e4m3: Wih_a[:,0:2048]*32
__device__ __align__(256) uint8_t g_f8Ahh[Gz*Dz];   // e4m3: Whh_a*32
__device__ __align__(256) uint8_t g_f8Lh [Gz*Dz];   // e4m3: Wih_l[:,0:2048]*32
__device__ __align__(256) uint8_t g_f8Lhh[Gz*Dz];   // e4m3: Whh_l*32
__device__ __align__(256) bf16 g_bAv [Gz*Dz];       // Wih_a[:,2048:4096] (v_bar block)
__device__ __align__(256) bf16 g_bAe [Gz*Dz];       // Wih_a[:,4096:6144] (emb block)
__device__ __align__(256) bf16 g_bLv [Gz*Dz];       // Wih_l[:,2048:4096] (v_hat block)
__device__ __align__(256) bf16 g_bFC [Vz*Dz];       // Wfc
__device__ __align__(256) bf16 g_embsB[Bz*Tz*Dz];   // [t*32+b, k]
__device__ __align__(256) bf16 g_vbarB[Bz*Dz];
__device__ __align__(256) bf16 g_vhatB[Bz*Dz];
__device__ __align__(256) uint8_t g_h8a[Bz*Dz];     // e4m3: h_a*8
__device__ __align__(256) uint8_t g_h8l[Bz*Dz];     // e4m3: h_l*8
__device__ __align__(256) bf16 g_hlAll[Tz*Bz*Dz];   // rows t*32+b (bf16 for logits GEMM)
__device__ __align__(256) float g_caF[Bz*Dz];
__device__ __align__(256) float g_clF[Bz*Dz];
__device__ __align__(256) float g_zF[5*Bz*Gz];      // 5 partial-z slabs
__device__ __align__(256) float g_prevAF[Bz*Gz];
__device__ __align__(256) float g_preLF[Bz*Gz];
__device__ __align__(256) float g_preAF[Bz*Tz*Gz];

struct JobSet8 {
    const uint8_t* A[3];
    const uint8_t* W[3];
    float*         Z[3];
    int            kOff[3];
};

struct ConvJobs {
    const float* src[8];
    void*        dst[8];
    int          stride[8];
    int          off[8];
    int          total4[8];
    int          isFp8[8];
};

__device__ __forceinline__ uint32_t smem_u32(const void* p) {
    return (uint32_t)__cvta_generic_to_shared(p);
}

// ---------------- prep: features reduction + embedding gather + state init --------------
// (kernel launch #1 — replaces 4 memsets + k_feat + k_embs)
__global__ void k_prep(const float* __restrict__ f, const float* __restrict__ emb,
                       const int* __restrict__ cap) {
    int i = blockIdx.x * 256 + threadIdx.x;
    if (i < Bz * Dz) {
        int b = i >> 11, k = i & 2047;
        const float* p = f + (size_t)b * Xz * Dz + k;
        float s = 0.f;
#pragma unroll
        for (int x = 0; x < Xz; x++) s += p[x * Dz];
        g_vbarB[i] = __float2bfloat16(s * (1.f / 36.f));
        g_vhatB[i] = __float2bfloat16(s);
        g_caF[i] = 0.f;
        g_clF[i] = 0.f;
        g_h8a[i] = 0;
        g_h8l[i] = 0;
    }
    if (i < Bz * Tz * Dz) {
        int k = i & 2047, r = i >> 11;
        int t = r >> 5, b = r & 31;
        int tok = cap[b * Tz + t];
        g_embsB[i] = __float2bfloat16(emb[(size_t)tok * Dz + k]);
    }
}

// ---------------- all 8 weight conversions in one launch (kernel launch #2) -------------
__global__ void k_convall(ConvJobs cj) {
    int j = blockIdx.y;
    int i = blockIdx.x * 256 + threadIdx.x;
    if (i >= cj.total4[j]) return;
    int base = i << 2;
    int n = base >> 11, k = base & 2047;
    const float* p = cj.src[j] + (size_t)n * cj.stride[j] + cj.off[j] + k;
    if (cj.isFp8[j]) {
        uint32_t b0 = __nv_cvt_float_to_fp8(p[0] * WSCALE, __NV_SATFINITE, __NV_E4M3);
        uint32_t b1 = __nv_cvt_float_to_fp8(p[1] * WSCALE, __NV_SATFINITE, __NV_E4M3);
        uint32_t b2 = __nv_cvt_float_to_fp8(p[2] * WSCALE, __NV_SATFINITE, __NV_E4M3);
        uint32_t b3 = __nv_cvt_float_to_fp8(p[3] * WSCALE, __NV_SATFINITE, __NV_E4M3);
        *(uint32_t*)((uint8_t*)cj.dst[j] + base) = b0 | (b1 << 8) | (b2 << 16) | (b3 << 24);
    } else {
        bf16* q = (bf16*)cj.dst[j] + base;
        q[0] = __float2bfloat16(p[0]);
        q[1] = __float2bfloat16(p[1]);
        q[2] = __float2bfloat16(p[2]);
        q[3] = __float2bfloat16(p[3]);
    }
}

#define STAGES 4

// ---------------- generic bf16 tensor-core GEMM (precompute + logits) ----------------
__global__ void __launch_bounds__(128)
k_gemm(const bf16* __restrict__ A1, const bf16* __restrict__ W1, int K1,
       const bf16* __restrict__ A2, const bf16* __restrict__ W2, int K2,
       const float* __restrict__ P, int ldP, int pLocal,
       const float* __restrict__ bias1, const float* __restrict__ bias2,
       float* __restrict__ Z, int ldZ, int N, int remapBT)
{
    __shared__ __align__(128) bf16 sA[STAGES][32 * 72];
    __shared__ __align__(128) bf16 sW[STAGES][32 * 72];

    const int tid   = threadIdx.x;
    const int lane  = tid & 31;
    const int warp  = tid >> 5;
    const int nBlk  = blockIdx.x * 32;
    const int mBase = blockIdx.y * 32;
    const int s1      = K1 >> 6;
    const int nStages = (K1 + K2) >> 6;

    const int lr0 = tid >> 3;
    const int lc  = (tid & 7) * 8;

    auto loadStage = [&](int s, int buf) {
        int kg = s << 6;
        const bf16* Ap; const bf16* Wp; int K; int ko;
        if (s < s1) { Ap = A1; Wp = W1; K = K1; ko = kg; }
        else        { Ap = A2; Wp = W2; K = K2; ko = kg - (s1 << 6); }
#pragma unroll
        for (int half = 0; half < 2; half++) {
            int row = lr0 + half * 16;
            uint32_t da = smem_u32(&sA[buf][row * 72 + lc]);
            const bf16* ga = Ap + (size_t)(mBase + row) * K + ko + lc;
            asm volatile("cp.async.cg.shared.global [%0], [%1], 16;\n" :: "r"(da), "l"(ga));
            int wr = nBlk + row;
            uint32_t dw = smem_u32(&sW[buf][row * 72 + lc]);
            const bf16* gw = W1 == nullptr ? nullptr : (Wp + (size_t)(wr < N ? wr : 0) * K + ko + lc);
            int sz = (wr < N) ? 16 : 0;
            asm volatile("cp.async.cg.shared.global [%0], [%1], 16, %2;\n"
                         :: "r"(dw), "l"(gw), "r"(sz));
        }
    };

#pragma unroll
    for (int s = 0; s < STAGES - 1; s++) {
        if (s < nStages) loadStage(s, s);
        asm volatile("cp.async.commit_group;\n");
    }

    float d0[4] = {0, 0, 0, 0}, d1[4] = {0, 0, 0, 0};
    const int aR = lane & 15;
    const int aC = (lane >> 4) * 8;
    const int bR = warp * 8 + (lane & 7);
    const int bC = ((lane >> 3) & 1) * 8;

    for (int s = 0; s < nStages; s++) {
        if (s + STAGES - 1 < nStages) loadStage(s + STAGES - 1, (s + STAGES - 1) % STAGES);
        asm volatile("cp.async.commit_group;\n");
        asm volatile("cp.async.wait_group %0;\n" :: "n"(STAGES - 1));
        __syncthreads();
        const bf16* pa = sA[s % STAGES];
        const bf16* pw = sW[s % STAGES];
#pragma unroll
        for (int kk = 0; kk < 64; kk += 16) {
            uint32_t a0[4], a1[4], bb[2];
            uint32_t ad0 = smem_u32(&pa[aR * 72 + kk + aC]);
            uint32_t ad1 = smem_u32(&pa[(aR + 16) * 72 + kk + aC]);
            uint32_t adb = smem_u32(&pw[bR * 72 + kk + bC]);
            asm volatile("ldmatrix.sync.aligned.m8n8.x4.shared.b16 {%0,%1,%2,%3}, [%4];\n"
                : "=r"(a0[0]), "=r"(a0[1]), "=r"(a0[2]), "=r"(a0[3]) : "r"(ad0));
            asm volatile("ldmatrix.sync.aligned.m8n8.x4.shared.b16 {%0,%1,%2,%3}, [%4];\n"
                : "=r"(a1[0]), "=r"(a1[1]), "=r"(a1[2]), "=r"(a1[3]) : "r"(ad1));
            asm volatile("ldmatrix.sync.aligned.m8n8.x2.shared.b16 {%0,%1}, [%2];\n"
                : "=r"(bb[0]), "=r"(bb[1]) : "r"(adb));
            asm volatile("mma.sync.aligned.m16n8k16.row.col.f32.bf16.bf16.f32 "
                "{%0,%1,%2,%3}, {%4,%5,%6,%7}, {%8,%9}, {%0,%1,%2,%3};\n"
                : "+f"(d0[0]), "+f"(d0[1]), "+f"(d0[2]), "+f"(d0[3])
                : "r"(a0[0]), "r"(a0[1]), "r"(a0[2]), "r"(a0[3]), "r"(bb[0]), "r"(bb[1]));
            asm volatile("mma.sync.aligned.m16n8k16.row.col.f32.bf16.bf16.f32 "
                "{%0,%1,%2,%3}, {%4,%5,%6,%7}, {%8,%9}, {%0,%1,%2,%3};\n"
                : "+f"(d1[0]), "+f"(d1[1]), "+f"(d1[2]), "+f"(d1[3])
                : "r"(a1[0]), "r"(a1[1]), "r"(a1[2]), "r"(a1[3]), "r"(bb[0]), "r"(bb[1]));
        }
        __syncthreads();
    }

    const int g = lane >> 2, tg = lane & 3;
    const int ncol = nBlk + warp * 8 + tg * 2;
#pragma unroll
    for (int mt = 0; mt < 2; mt++) {
        const float* dd = mt ? d1 : d0;
#pragma unroll
        for (int rr = 0; rr < 2; rr++) {
            int m = mt * 16 + rr * 8 + g;
            int row = mBase + m;
            int prow = pLocal ? (row & 31) : row;
            int orow = remapBT ? ((row & 31) * Tz + (row >> 5)) : row;
#pragma unroll
            for (int cc = 0; cc < 2; cc++) {
                int col = ncol + cc;
                if (col < N) {
                    float v = dd[rr * 2 + cc];
                    if (P)     v += P[(size_t)prow * ldP + col];
                    if (bias1) v += bias1[col];
                    if (bias2) v += bias2[col];
                    Z[(size_t)orow * ldZ + col] = v;
                }
            }
        }
    }
}

// ---------------- fp8 job-packed step GEMM (identical to R8) ----------------
__global__ void __launch_bounds__(128)
k_gemmJ8(JobSet8 js, int kLen)
{
    __shared__ __align__(128) uint8_t sA[STAGES][32 * 144];
    __shared__ __align__(128) uint8_t sW[STAGES][32 * 144];

    const int tid   = threadIdx.x;
    const int lane  = tid & 31;
    const int warp  = tid >> 5;
    const int nBlk  = blockIdx.x * 32;
    const int nStages = kLen >> 7;

    const uint8_t* A = js.A[blockIdx.y];
    const uint8_t* W = js.W[blockIdx.y];
    float*         Z = js.Z[blockIdx.y];
    const int kOff = js.kOff[blockIdx.y];

    const int lr0 = tid >> 3;
    const int lc  = (tid & 7) * 16;

    auto loadStage = [&](int s, int buf) {
        int ko = (s << 7) + kOff;
#pragma unroll
        for (int half = 0; half < 2; half++) {
            int row = lr0 + half * 16;
            uint32_t da = smem_u32(&sA[buf][row * 144 + lc]);
            const uint8_t* ga = A + (size_t)row * Dz + ko + lc;
            asm volatile("cp.async.cg.shared.global [%0], [%1], 16;\n" :: "r"(da), "l"(ga));
            uint32_t dw = smem_u32(&sW[buf][row * 144 + lc]);
            const uint8_t* gw = W + (size_t)(nBlk + row) * Dz + ko + lc;
            asm volatile("cp.async.cg.shared.global [%0], [%1], 16;\n" :: "r"(dw), "l"(gw));
        }
    };

#pragma unroll
    for (int s = 0; s < STAGES - 1; s++) {
        if (s < nStages) loadStage(s, s);
        asm volatile("cp.async.commit_group;\n");
    }

    float d0[4] = {0, 0, 0, 0}, d1[4] = {0, 0, 0, 0};
    const int aR  = lane & 15;
    const int aCB = (lane >> 4) * 16;
    const int bR  = warp * 8 + (lane & 7);
    const int bCB = ((lane >> 3) & 1) * 16;

    for (int s = 0; s < nStages; s++) {
        if (s + STAGES - 1 < nStages) loadStage(s + STAGES - 1, (s + STAGES - 1) % STAGES);
        asm volatile("cp.async.commit_group;\n");
        asm volatile("cp.async.wait_group %0;\n" :: "n"(STAGES - 1));
        __syncthreads();
        const uint8_t* pa = sA[s % STAGES];
        const uint8_t* pw = sW[s % STAGES];
#pragma unroll
        for (int kk = 0; kk < 128; kk += 32) {
            uint32_t a0[4], a1[4], bb[2];
            uint32_t ad0 = smem_u32(&pa[aR * 144 + kk + aCB]);
            uint32_t ad1 = smem_u32(&pa[(aR + 16) * 144 + kk + aCB]);
            uint32_t adb = smem_u32(&pw[bR * 144 + kk + bCB]);
            asm volatile("ldmatrix.sync.aligned.m8n8.x4.shared.b16 {%0,%1,%2,%3}, [%4];\n"
                : "=r"(a0[0]), "=r"(a0[1]), "=r"(a0[2]), "=r"(a0[3]) : "r"(ad0));
            asm volatile("ldmatrix.sync.aligned.m8n8.x4.shared.b16 {%0,%1,%2,%3}, [%4];\n"
                : "=r"(a1[0]), "=r"(a1[1]), "=r"(a1[2]), "=r"(a1[3]) : "r"(ad1));
            asm volatile("ldmatrix.sync.aligned.m8n8.x2.shared.b16 {%0,%1}, [%2];\n"
                : "=r"(bb[0]), "=r"(bb[1]) : "r"(adb));
            asm volatile("mma.sync.aligned.m16n8k32.row.col.f32.e4m3.e4m3.f32 "
                "{%0,%1,%2,%3}, {%4,%5,%6,%7}, {%8,%9}, {%0,%1,%2,%3};\n"
                : "+f"(d0[0]), "+f"(d0[1]), "+f"(d0[2]), "+f"(d0[3])
                : "r"(a0[0]), "r"(a0[1]), "r"(a0[2]), "r"(a0[3]), "r"(bb[0]), "r"(bb[1]));
            asm volatile("mma.sync.aligned.m16n8k32.row.col.f32.e4m3.e4m3.f32 "
                "{%0,%1,%2,%3}, {%4,%5,%6,%7}, {%8,%9}, {%0,%1,%2,%3};\n"
                : "+f"(d1[0]), "+f"(d1[1]), "+f"(d1[2]), "+f"(d1[3])
                : "r"(a1[0]), "r"(a1[1]), "r"(a1[2]), "r"(a1[3]), "r"(bb[0]), "r"(bb[1]));
        }
        __syncthreads();
    }

    const int g = lane >> 2, tg = lane & 3;
    const int ncol = nBlk + warp * 8 + tg * 2;
#pragma unroll
    for (int mt = 0; mt < 2; mt++) {
        const float* dd = mt ? d1 : d0;
#pragma unroll
        for (int rr = 0; rr < 2; rr++) {
            int m = mt * 16 + rr * 8 + g;
#pragma unroll
            for (int cc = 0; cc < 2; cc++) {
                int col = ncol + cc;
                Z[(size_t)m * Gz + col] = dd[rr * 2 + cc] * UNSCALE;
            }
        }
    }
}

// ---------------- LSTM cell: z = z0 + z1 (+z2) + pre (identical to R8) ----------------
__global__ void k_cell(const float* __restrict__ z0, const float* __restrict__ z1,
                       const float* __restrict__ z2, const float* __restrict__ pre,
                       float* __restrict__ c, uint8_t* __restrict__ h8,
                       bf16* __restrict__ hCopy) {
    int i = blockIdx.x * 256 + threadIdx.x;
    if (i >= Bz * Dz) return;
    int b = i >> 11, d = i & 2047;
    size_t o = (size_t)b * Gz + d;
    float ii = z0[o]          + z1[o]          + pre[o];
    float ff = z0[o + Dz]     + z1[o + Dz]     + pre[o + Dz];
    float gg = z0[o + 2 * Dz] + z1[o + 2 * Dz] + pre[o + 2 * Dz];
    float oo = z0[o + 3 * Dz] + z1[o + 3 * Dz] + pre[o + 3 * Dz];
    if (z2) {
        ii += z2[o];
        ff += z2[o + Dz];
        gg += z2[o + 2 * Dz];
        oo += z2[o + 3 * Dz];
    }
    float si = 1.f / (1.f + expf(-ii));
    float sf = 1.f / (1.f + expf(-ff));
    float so = 1.f / (1.f + expf(-oo));
    float tg = tanhf(gg);
    float cn = sf * c[i] + si * tg;
    c[i] = cn;
    float hv = so * tanhf(cn);
    h8[i] = __nv_cvt_float_to_fp8(hv * HSCALE, __NV_SATFINITE, __NV_E4M3);
    if (hCopy) hCopy[i] = __float2bfloat16(hv);
}

// ---------------- in-place log_softmax over V per (b,t) row ----------------
__global__ void k_lsm(float* __restrict__ out) {
    __shared__ float red[8];
    int r = blockIdx.x;
    float* p = out + (size_t)r * Vz;
    int tid = threadIdx.x;
    float m = -1e30f;
    for (int i = tid; i < Vz; i += 256) m = fmaxf(m, p[i]);
#pragma unroll
    for (int o = 16; o > 0; o >>= 1) m = fmaxf(m, __shfl_xor_sync(0xffffffffu, m, o));
    if ((tid & 31) == 0) red[tid >> 5] = m;
    __syncthreads();
    if (tid == 0) {
        float mm = red[0];
        for (int j = 1; j < 8; j++) mm = fmaxf(mm, red[j]);
        red[0] = mm;
    }
    __syncthreads();
    m = red[0];
    __syncthreads();
    float s = 0.f;
    for (int i = tid; i < Vz; i += 256) s += expf(p[i] - m);
#pragma unroll
    for (int o = 16; o > 0; o >>= 1) s += __shfl_xor_sync(0xffffffffu, s, o);
    if ((tid & 31) == 0) red[tid >> 5] = s;
    __syncthreads();
    if (tid == 0) {
        float ss = 0.f;
        for (int j = 0; j < 8; j++) ss += red[j];
        red[0] = ss;
    }
    __syncthreads();
    float lse = m + logf(red[0]);
    for (int i = tid; i < Vz; i += 256) p[i] -= lse;
}

// ---------------- host ----------------
extern "C" void kernel_launch(void* const* d_in, const int* in_sizes, int n_in,
                              void* d_out, int out_size) {
    const float* features = (const float*)d_in[0];
    const int*   caption  = (const int*)  d_in[1];
    const float* emb      = (const float*)d_in[2];
    const float* Wih_a    = (const float*)d_in[3];
    const float* Whh_a    = (const float*)d_in[4];
    const float* bih_a    = (const float*)d_in[5];
    const float* bhh_a    = (const float*)d_in[6];
    const float* Wih_l    = (const float*)d_in[7];
    const float* Whh_l    = (const float*)d_in[8];
    const float* bih_l    = (const float*)d_in[9];
    const float* bhh_l    = (const float*)d_in[10];
    const float* Wfc      = (const float*)d_in[17];
    const float* bfc      = (const float*)d_in[18];
    float* out = (float*)d_out;

    uint8_t *f8Ah, *f8Ahh, *f8Lh, *f8Lhh, *h8a, *h8l;
    bf16 *bAv, *bAe, *bLv, *bFC, *embsB, *vbarB, *vhatB, *hlAll;
    float *ca, *cl, *zz, *prevA, *preL, *preA;
    cudaGetSymbolAddress((void**)&f8Ah,  g_f8Ah);
    cudaGetSymbolAddress((void**)&f8Ahh, g_f8Ahh);
    cudaGetSymbolAddress((void**)&f8Lh,  g_f8Lh);
    cudaGetSymbolAddress((void**)&f8Lhh, g_f8Lhh);
    cudaGetSymbolAddress((void**)&h8a,   g_h8a);
    cudaGetSymbolAddress((void**)&h8l,   g_h8l);
    cudaGetSymbolAddress((void**)&bAv,   g_bAv);
    cudaGetSymbolAddress((void**)&bAe,   g_bAe);
    cudaGetSymbolAddress((void**)&bLv,   g_bLv);
    cudaGetSymbolAddress((void**)&bFC,   g_bFC);
    cudaGetSymbolAddress((void**)&embsB, g_embsB);
    cudaGetSymbolAddress((void**)&vbarB, g_vbarB);
    cudaGetSymbolAddress((void**)&vhatB, g_vhatB);
    cudaGetSymbolAddress((void**)&hlAll, g_hlAll);
    cudaGetSymbolAddress((void**)&ca,    g_caF);
    cudaGetSymbolAddress((void**)&cl,    g_clF);
    cudaGetSymbolAddress((void**)&zz,    g_zF);
    cudaGetSymbolAddress((void**)&prevA, g_prevAF);
    cudaGetSymbolAddress((void**)&preL,  g_preLF);
    cudaGetSymbolAddress((void**)&preA,  g_preAF);

    const size_t SLAB = (size_t)Bz * Gz;
    dim3 blk(128);

    // launch #1: feat + embs + state zero-init
    k_prep<<<(Bz * Tz * Dz + 255) / 256, 256>>>(features, emb, caption);

    // launch #2: all 8 weight conversions
    ConvJobs cj;
    const int cv4 = Gz * Dz / 4;             // 4M quads for 8192x2048 weights
    const int cvFC = Vz * Dz / 4;            // 5.12M quads for Wfc
    cj.src[0] = Wih_a; cj.dst[0] = f8Ah;  cj.stride[0] = 3 * Dz; cj.off[0] = 0;      cj.total4[0] = cv4;  cj.isFp8[0] = 1;
    cj.src[1] = Whh_a; cj.dst[1] = f8Ahh; cj.stride[1] = Dz;     cj.off[1] = 0;      cj.total4[1] = cv4;  cj.isFp8[1] = 1;
    cj.src[2] = Wih_l; cj.dst[2] = f8Lh;  cj.stride[2] = 2 * Dz; cj.off[2] = 0;      cj.total4[2] = cv4;  cj.isFp8[2] = 1;
    cj.src[3] = Whh_l; cj.dst[3] = f8Lhh; cj.stride[3] = Dz;     cj.off[3] = 0;      cj.total4[3] = cv4;  cj.isFp8[3] = 1;
    cj.src[4] = Wih_a; cj.dst[4] = bAv;   cj.stride[4] = 3 * Dz; cj.off[4] = Dz;     cj.total4[4] = cv4;  cj.isFp8[4] = 0;
    cj.src[5] = Wih_a; cj.dst[5] = bAe;   cj.stride[5] = 3 * Dz; cj.off[5] = 2 * Dz; cj.total4[5] = cv4;  cj.isFp8[5] = 0;
    cj.src[6] = Wih_l; cj.dst[6] = bLv;   cj.stride[6] = 2 * Dz; cj.off[6] = Dz;     cj.total4[6] = cv4;  cj.isFp8[6] = 0;
    cj.src[7] = Wfc;   cj.dst[7] = bFC;   cj.stride[7] = Dz;     cj.off[7] = 0;      cj.total4[7] = cvFC; cj.isFp8[7] = 0;
    k_convall<<<dim3((cvFC + 255) / 256, 8), 256>>>(cj);

    // launches #3-#5: pre-activation GEMMs (bf16)
    k_gemm<<<dim3(Gz / 32, 1), blk>>>(vbarB, bAv, Dz, vbarB, bAv, 0,
                                      nullptr, 0, 0, bih_a, bhh_a, prevA, Gz, Gz, 0);
    k_gemm<<<dim3(Gz / 32, Tz), blk>>>(embsB, bAe, Dz, embsB, bAe, 0,
                                       prevA, Gz, 1, nullptr, nullptr, preA, Gz, Gz, 0);
    k_gemm<<<dim3(Gz / 32, 1), blk>>>(vhatB, bLv, Dz, vhatB, bLv, 0,
                                      nullptr, 0, 0, bih_l, bhh_l, preL, Gz, Gz, 0);

    // launch #6 onward: the recurrent loop (launch #6 = first k_gemmJ8 -> ncu -s 5 target)
    for (int t = 0; t < Tz; t++) {
        JobSet8 jx;
        jx.A[0] = h8l;  jx.W[0] = f8Ah;   jx.Z[0] = zz;             jx.kOff[0] = 0;
        jx.A[1] = h8a;  jx.W[1] = f8Ahh;  jx.Z[1] = zz + SLAB;      jx.kOff[1] = 0;
        jx.A[2] = h8l;  jx.W[2] = f8Lhh;  jx.Z[2] = zz + 2 * SLAB;  jx.kOff[2] = 0;
        k_gemmJ8<<<dim3(Gz / 32, 3), blk>>>(jx, Dz);
        k_cell<<<(Bz * Dz + 255) / 256, 256>>>(zz, zz + SLAB, nullptr,
                                               preA + (size_t)t * SLAB,
                                               ca, h8a, nullptr);
        JobSet8 jy;
        jy.A[0] = h8a;  jy.W[0] = f8Lh;  jy.Z[0] = zz + 3 * SLAB;  jy.kOff[0] = 0;
        jy.A[1] = h8a;  jy.W[1] = f8Lh;  jy.Z[1] = zz + 4 * SLAB;  jy.kOff[1] = 1024;
        jy.A[2] = h8a;  jy.W[2] = f8Lh;  jy.Z[2] = zz + 4 * SLAB;  jy.kOff[2] = 1024;
        k_gemmJ8<<<dim3(Gz / 32, 2), blk>>>(jy, 1024);
        k_cell<<<(Bz * Dz + 255) / 256, 256>>>(zz + 2 * SLAB, zz + 3 * SLAB,
                                               zz + 4 * SLAB, preL,
                                               cl, h8l, hlAll + (size_t)t * Bz * Dz);
    }

    // batched logits: rows r=t*32+b of hlAll @ Wfc^T + bfc -> out[b][t][:]
    k_gemm<<<dim3((Vz + 31) / 32, Tz), blk>>>(hlAll, bFC, Dz, hlAll, bFC, 0,
                                              nullptr, 0, 0, bfc, nullptr,
                                              out, Vz, Vz, 1);
    k_lsm<<<Bz * Tz, 256>>>(out);
}

// round 14
// speedup vs baseline: 1.2829x; 1.0405x over previous
#include <cuda_runtime.h>
#include <cuda_bf16.h>
#include <cuda_fp8.h>
#include <cstdint>
#include <math.h>

typedef __nv_bfloat16 bf16;

#define Bz 32
#define Dz 2048
#define Gz 8192
#define Vz 10000
#define Tz 20
#define Xz 36

#define WSCALE 32.f
#define HSCALE 8.f
#define UNSCALE (1.f / 256.f)

// ---------------- device scratch ----------------
__device__ __align__(256) uint8_t g_f8Ah [Gz*Dz];
__device__ __align__(256) uint8_t g_f8Ahh[Gz*Dz];
__device__ __align__(256) uint8_t g_f8Lh [Gz*Dz];
__device__ __align__(256) uint8_t g_f8Lhh[Gz*Dz];
__device__ __align__(256) bf16 g_bAv [Gz*Dz];
__device__ __align__(256) bf16 g_bAe [Gz*Dz];
__device__ __align__(256) bf16 g_bLv [Gz*Dz];
__device__ __align__(256) bf16 g_bFC [Vz*Dz];
__device__ __align__(256) bf16 g_embsB[Bz*Tz*Dz];
__device__ __align__(256) bf16 g_vbarB[Bz*Dz];
__device__ __align__(256) bf16 g_vhatB[Bz*Dz];
__device__ __align__(256) uint8_t g_h8a[Bz*Dz];
__device__ __align__(256) uint8_t g_h8l[Bz*Dz];
__device__ __align__(256) bf16 g_hlAll[Tz*Bz*Dz];
__device__ __align__(256) float g_caF[Bz*Dz];
__device__ __align__(256) float g_clF[Bz*Dz];
__device__ __align__(256) float g_zF[5*Bz*Gz];
__device__ __align__(256) float g_prevAF[Bz*Gz];
__device__ __align__(256) float g_preLF[Bz*Gz];
__device__ __align__(256) float g_preAF[Bz*Tz*Gz];

struct JobSet8 {
    const uint8_t* A[3];
    const uint8_t* W[3];
    float*         Z[3];
    int            kOff[3];
};

struct ConvJobs {
    const float* src[8];
    void*        dst[8];
    int          stride[8];
    int          off[8];
    int          total4[8];
    int          isFp8[8];
};

__device__ __forceinline__ uint32_t smem_u32(const void* p) {
    return (uint32_t)__cvta_generic_to_shared(p);
}

// ---------------- prep: features reduction + embedding gather + state init --------------
__global__ void k_prep(const float* __restrict__ f, const float* __restrict__ emb,
                       const int* __restrict__ cap) {
    int i = blockIdx.x * 256 + threadIdx.x;
    if (i < Bz * Dz) {
        int b = i >> 11, k = i & 2047;
        const float* p = f + (size_t)b * Xz * Dz + k;
        float s = 0.f;
#pragma unroll
        for (int x = 0; x < Xz; x++) s += p[x * Dz];
        g_vbarB[i] = __float2bfloat16(s * (1.f / 36.f));
        g_vhatB[i] = __float2bfloat16(s);
        g_caF[i] = 0.f;
        g_clF[i] = 0.f;
        g_h8a[i] = 0;
        g_h8l[i] = 0;
    }
    if (i < Bz * Tz * Dz) {
        int k = i & 2047, r = i >> 11;
        int t = r >> 5, b = r & 31;
        int tok = cap[b * Tz + t];
        g_embsB[i] = __float2bfloat16(emb[(size_t)tok * Dz + k]);
    }
}

// ---------------- all 8 weight conversions in one launch ----------------
__global__ void k_convall(ConvJobs cj) {
    int j = blockIdx.y;
    int i = blockIdx.x * 256 + threadIdx.x;
    if (i >= cj.total4[j]) return;
    int base = i << 2;
    int n = base >> 11, k = base & 2047;
    const float* p = cj.src[j] + (size_t)n * cj.stride[j] + cj.off[j] + k;
    if (cj.isFp8[j]) {
        uint32_t b0 = __nv_cvt_float_to_fp8(p[0] * WSCALE, __NV_SATFINITE, __NV_E4M3);
        uint32_t b1 = __nv_cvt_float_to_fp8(p[1] * WSCALE, __NV_SATFINITE, __NV_E4M3);
        uint32_t b2 = __nv_cvt_float_to_fp8(p[2] * WSCALE, __NV_SATFINITE, __NV_E4M3);
        uint32_t b3 = __nv_cvt_float_to_fp8(p[3] * WSCALE, __NV_SATFINITE, __NV_E4M3);
        *(uint32_t*)((uint8_t*)cj.dst[j] + base) = b0 | (b1 << 8) | (b2 << 16) | (b3 << 24);
    } else {
        bf16* q = (bf16*)cj.dst[j] + base;
        q[0] = __float2bfloat16(p[0]);
        q[1] = __float2bfloat16(p[1]);
        q[2] = __float2bfloat16(p[2]);
        q[3] = __float2bfloat16(p[3]);
    }
}

#define STAGES 4

// ---------------- generic bf16 GEMM, M=32 tile (prevA / preL only) ----------------
__global__ void __launch_bounds__(128)
k_gemm(const bf16* __restrict__ A1, const bf16* __restrict__ W1, int K1,
       const float* __restrict__ bias1, const float* __restrict__ bias2,
       float* __restrict__ Z, int ldZ, int N)
{
    __shared__ __align__(128) bf16 sA[STAGES][32 * 72];
    __shared__ __align__(128) bf16 sW[STAGES][32 * 72];

    const int tid   = threadIdx.x;
    const int lane  = tid & 31;
    const int warp  = tid >> 5;
    const int nBlk  = blockIdx.x * 32;
    const int nStages = K1 >> 6;

    const int lr0 = tid >> 3;
    const int lc  = (tid & 7) * 8;

    auto loadStage = [&](int s, int buf) {
        int ko = s << 6;
#pragma unroll
        for (int half = 0; half < 2; half++) {
            int row = lr0 + half * 16;
            uint32_t da = smem_u32(&sA[buf][row * 72 + lc]);
            const bf16* ga = A1 + (size_t)row * K1 + ko + lc;
            asm volatile("cp.async.cg.shared.global [%0], [%1], 16;\n" :: "r"(da), "l"(ga));
            int wr = nBlk + row;
            uint32_t dw = smem_u32(&sW[buf][row * 72 + lc]);
            const bf16* gw = W1 + (size_t)(wr < N ? wr : 0) * K1 + ko + lc;
            int sz = (wr < N) ? 16 : 0;
            asm volatile("cp.async.cg.shared.global [%0], [%1], 16, %2;\n"
                         :: "r"(dw), "l"(gw), "r"(sz));
        }
    };

#pragma unroll
    for (int s = 0; s < STAGES - 1; s++) {
        if (s < nStages) loadStage(s, s);
        asm volatile("cp.async.commit_group;\n");
    }

    float d0[4] = {0, 0, 0, 0}, d1[4] = {0, 0, 0, 0};
    const int aR = lane & 15;
    const int aC = (lane >> 4) * 8;
    const int bR = warp * 8 + (lane & 7);
    const int bC = ((lane >> 3) & 1) * 8;

    for (int s = 0; s < nStages; s++) {
        if (s + STAGES - 1 < nStages) loadStage(s + STAGES - 1, (s + STAGES - 1) % STAGES);
        asm volatile("cp.async.commit_group;\n");
        asm volatile("cp.async.wait_group %0;\n" :: "n"(STAGES - 1));
        __syncthreads();
        const bf16* pa = sA[s % STAGES];
        const bf16* pw = sW[s % STAGES];
#pragma unroll
        for (int kk = 0; kk < 64; kk += 16) {
            uint32_t a0[4], a1[4], bb[2];
            uint32_t ad0 = smem_u32(&pa[aR * 72 + kk + aC]);
            uint32_t ad1 = smem_u32(&pa[(aR + 16) * 72 + kk + aC]);
            uint32_t adb = smem_u32(&pw[bR * 72 + kk + bC]);
            asm volatile("ldmatrix.sync.aligned.m8n8.x4.shared.b16 {%0,%1,%2,%3}, [%4];\n"
                : "=r"(a0[0]), "=r"(a0[1]), "=r"(a0[2]), "=r"(a0[3]) : "r"(ad0));
            asm volatile("ldmatrix.sync.aligned.m8n8.x4.shared.b16 {%0,%1,%2,%3}, [%4];\n"
                : "=r"(a1[0]), "=r"(a1[1]), "=r"(a1[2]), "=r"(a1[3]) : "r"(ad1));
            asm volatile("ldmatrix.sync.aligned.m8n8.x2.shared.b16 {%0,%1}, [%2];\n"
                : "=r"(bb[0]), "=r"(bb[1]) : "r"(adb));
            asm volatile("mma.sync.aligned.m16n8k16.row.col.f32.bf16.bf16.f32 "
                "{%0,%1,%2,%3}, {%4,%5,%6,%7}, {%8,%9}, {%0,%1,%2,%3};\n"
                : "+f"(d0[0]), "+f"(d0[1]), "+f"(d0[2]), "+f"(d0[3])
                : "r"(a0[0]), "r"(a0[1]), "r"(a0[2]), "r"(a0[3]), "r"(bb[0]), "r"(bb[1]));
            asm volatile("mma.sync.aligned.m16n8k16.row.col.f32.bf16.bf16.f32 "
                "{%0,%1,%2,%3}, {%4,%5,%6,%7}, {%8,%9}, {%0,%1,%2,%3};\n"
                : "+f"(d1[0]), "+f"(d1[1]), "+f"(d1[2]), "+f"(d1[3])
                : "r"(a1[0]), "r"(a1[1]), "r"(a1[2]), "r"(a1[3]), "r"(bb[0]), "r"(bb[1]));
        }
        __syncthreads();
    }

    const int g = lane >> 2, tg = lane & 3;
    const int ncol = nBlk + warp * 8 + tg * 2;
#pragma unroll
    for (int mt = 0; mt < 2; mt++) {
        const float* dd = mt ? d1 : d0;
#pragma unroll
        for (int rr = 0; rr < 2; rr++) {
            int row = mt * 16 + rr * 8 + g;
#pragma unroll
            for (int cc = 0; cc < 2; cc++) {
                int col = ncol + cc;
                if (col < N) {
                    float v = dd[rr * 2 + cc];
                    if (bias1) v += bias1[col];
                    if (bias2) v += bias2[col];
                    Z[(size_t)row * ldZ + col] = v;
                }
            }
        }
    }
}

#define BSTAGES 2

// ---------------- big-M bf16 GEMM: M=128 tile x N=32, 4 M-subtiles share weight stage ----
// Fixes the grid.y weight re-read pathology of preA / logits (M=640).
__global__ void __launch_bounds__(128)
k_gemmBig(const bf16* __restrict__ A, const bf16* __restrict__ W, int K,
          const float* __restrict__ P, int ldP, int pLocal,
          const float* __restrict__ bias,
          float* __restrict__ Z, int ldZ, int N, int remapBT)
{
    __shared__ __align__(128) bf16 sA[BSTAGES][128 * 72];
    __shared__ __align__(128) bf16 sW[BSTAGES][32 * 72];

    const int tid   = threadIdx.x;
    const int lane  = tid & 31;
    const int warp  = tid >> 5;
    const int nBlk  = blockIdx.x * 32;
    const int mBase = blockIdx.y * 128;
    const int nStages = K >> 6;

    const int lr0 = tid >> 3;        // 0..15
    const int lc  = (tid & 7) * 8;

    auto loadStage = [&](int s, int buf) {
        int ko = s << 6;
#pragma unroll
        for (int q = 0; q < 8; q++) {              // 128 A rows: q*16 + lr0
            int row = q * 16 + lr0;
            uint32_t da = smem_u32(&sA[buf][row * 72 + lc]);
            const bf16* ga = A + (size_t)(mBase + row) * K + ko + lc;
            asm volatile("cp.async.cg.shared.global [%0], [%1], 16;\n" :: "r"(da), "l"(ga));
        }
#pragma unroll
        for (int half = 0; half < 2; half++) {
            int row = lr0 + half * 16;
            int wr = nBlk + row;
            uint32_t dw = smem_u32(&sW[buf][row * 72 + lc]);
            const bf16* gw = W + (size_t)(wr < N ? wr : 0) * K + ko + lc;
            int sz = (wr < N) ? 16 : 0;
            asm volatile("cp.async.cg.shared.global [%0], [%1], 16, %2;\n"
                         :: "r"(dw), "l"(gw), "r"(sz));
        }
    };

    loadStage(0, 0);
    asm volatile("cp.async.commit_group;\n");

    float acc[4][8];
#pragma unroll
    for (int su = 0; su < 4; su++)
#pragma unroll
        for (int q = 0; q < 8; q++) acc[su][q] = 0.f;

    const int aR = lane & 15;
    const int aC = (lane >> 4) * 8;
    const int bR = warp * 8 + (lane & 7);
    const int bC = ((lane >> 3) & 1) * 8;

    for (int s = 0; s < nStages; s++) {
        if (s + 1 < nStages) loadStage(s + 1, (s + 1) & 1);
        asm volatile("cp.async.commit_group;\n");
        asm volatile("cp.async.wait_group 1;\n");
        __syncthreads();
        const bf16* pa = sA[s & 1];
        const bf16* pw = sW[s & 1];
#pragma unroll
        for (int kk = 0; kk < 64; kk += 16) {
            uint32_t bb[2];
            uint32_t adb = smem_u32(&pw[bR * 72 + kk + bC]);
            asm volatile("ldmatrix.sync.aligned.m8n8.x2.shared.b16 {%0,%1}, [%2];\n"
                : "=r"(bb[0]), "=r"(bb[1]) : "r"(adb));
#pragma unroll
            for (int su = 0; su < 4; su++) {
                uint32_t a0[4], a1[4];
                uint32_t ad0 = smem_u32(&pa[(su * 32 + aR) * 72 + kk + aC]);
                uint32_t ad1 = smem_u32(&pa[(su * 32 + 16 + aR) * 72 + kk + aC]);
                asm volatile("ldmatrix.sync.aligned.m8n8.x4.shared.b16 {%0,%1,%2,%3}, [%4];\n"
                    : "=r"(a0[0]), "=r"(a0[1]), "=r"(a0[2]), "=r"(a0[3]) : "r"(ad0));
                asm volatile("ldmatrix.sync.aligned.m8n8.x4.shared.b16 {%0,%1,%2,%3}, [%4];\n"
                    : "=r"(a1[0]), "=r"(a1[1]), "=r"(a1[2]), "=r"(a1[3]) : "r"(ad1));
                asm volatile("mma.sync.aligned.m16n8k16.row.col.f32.bf16.bf16.f32 "
                    "{%0,%1,%2,%3}, {%4,%5,%6,%7}, {%8,%9}, {%0,%1,%2,%3};\n"
                    : "+f"(acc[su][0]), "+f"(acc[su][1]), "+f"(acc[su][2]), "+f"(acc[su][3])
                    : "r"(a0[0]), "r"(a0[1]), "r"(a0[2]), "r"(a0[3]), "r"(bb[0]), "r"(bb[1]));
                asm volatile("mma.sync.aligned.m16n8k16.row.col.f32.bf16.bf16.f32 "
                    "{%0,%1,%2,%3}, {%4,%5,%6,%7}, {%8,%9}, {%0,%1,%2,%3};\n"
                    : "+f"(acc[su][4]), "+f"(acc[su][5]), "+f"(acc[su][6]), "+f"(acc[su][7])
                    : "r"(a1[0]), "r"(a1[1]), "r"(a1[2]), "r"(a1[3]), "r"(bb[0]), "r"(bb[1]));
            }
        }
        __syncthreads();
    }

    const int g = lane >> 2, tg = lane & 3;
    const int ncol = nBlk + warp * 8 + tg * 2;
#pragma unroll
    for (int su = 0; su < 4; su++) {
#pragma unroll
        for (int mt = 0; mt < 2; mt++) {
#pragma unroll
            for (int rr = 0; rr < 2; rr++) {
                int row = mBase + su * 32 + mt * 16 + rr * 8 + g;
                int prow = pLocal ? (row & 31) : row;
                int orow = remapBT ? ((row & 31) * Tz + (row >> 5)) : row;
#pragma unroll
                for (int cc = 0; cc < 2; cc++) {
                    int col = ncol + cc;
                    if (col < N) {
                        float v = acc[su][mt * 4 + rr * 2 + cc];
                        if (P)    v += P[(size_t)prow * ldP + col];
                        if (bias) v += bias[col];
                        Z[(size_t)orow * ldZ + col] = v;
                    }
                }
            }
        }
    }
}

// ---------------- fp8 job-packed step GEMM (identical to R8) ----------------
__global__ void __launch_bounds__(128)
k_gemmJ8(JobSet8 js, int kLen)
{
    __shared__ __align__(128) uint8_t sA[STAGES][32 * 144];
    __shared__ __align__(128) uint8_t sW[STAGES][32 * 144];

    const int tid   = threadIdx.x;
    const int lane  = tid & 31;
    const int warp  = tid >> 5;
    const int nBlk  = blockIdx.x * 32;
    const int nStages = kLen >> 7;

    const uint8_t* A = js.A[blockIdx.y];
    const uint8_t* W = js.W[blockIdx.y];
    float*         Z = js.Z[blockIdx.y];
    const int kOff = js.kOff[blockIdx.y];

    const int lr0 = tid >> 3;
    const int lc  = (tid & 7) * 16;

    auto loadStage = [&](int s, int buf) {
        int ko = (s << 7) + kOff;
#pragma unroll
        for (int half = 0; half < 2; half++) {
            int row = lr0 + half * 16;
            uint32_t da = smem_u32(&sA[buf][row * 144 + lc]);
            const uint8_t* ga = A + (size_t)row * Dz + ko + lc;
            asm volatile("cp.async.cg.shared.global [%0], [%1], 16;\n" :: "r"(da), "l"(ga));
            uint32_t dw = smem_u32(&sW[buf][row * 144 + lc]);
            const uint8_t* gw = W + (size_t)(nBlk + row) * Dz + ko + lc;
            asm volatile("cp.async.cg.shared.global [%0], [%1], 16;\n" :: "r"(dw), "l"(gw));
        }
    };

#pragma unroll
    for (int s = 0; s < STAGES - 1; s++) {
        if (s < nStages) loadStage(s, s);
        asm volatile("cp.async.commit_group;\n");
    }

    float d0[4] = {0, 0, 0, 0}, d1[4] = {0, 0, 0, 0};
    const int aR  = lane & 15;
    const int aCB = (lane >> 4) * 16;
    const int bR  = warp * 8 + (lane & 7);
    const int bCB = ((lane >> 3) & 1) * 16;

    for (int s = 0; s < nStages; s++) {
        if (s + STAGES - 1 < nStages) loadStage(s + STAGES - 1, (s + STAGES - 1) % STAGES);
        asm volatile("cp.async.commit_group;\n");
        asm volatile("cp.async.wait_group %0;\n" :: "n"(STAGES - 1));
        __syncthreads();
        const uint8_t* pa = sA[s % STAGES];
        const uint8_t* pw = sW[s % STAGES];
#pragma unroll
        for (int kk = 0; kk < 128; kk += 32) {
            uint32_t a0[4], a1[4], bb[2];
            uint32_t ad0 = smem_u32(&pa[aR * 144 + kk + aCB]);
            uint32_t ad1 = smem_u32(&pa[(aR + 16) * 144 + kk + aCB]);
            uint32_t adb = smem_u32(&pw[bR * 144 + kk + bCB]);
            asm volatile("ldmatrix.sync.aligned.m8n8.x4.shared.b16 {%0,%1,%2,%3}, [%4];\n"
                : "=r"(a0[0]), "=r"(a0[1]), "=r"(a0[2]), "=r"(a0[3]) : "r"(ad0));
            asm volatile("ldmatrix.sync.aligned.m8n8.x4.shared.b16 {%0,%1,%2,%3}, [%4];\n"
                : "=r"(a1[0]), "=r"(a1[1]), "=r"(a1[2]), "=r"(a1[3]) : "r"(ad1));
            asm volatile("ldmatrix.sync.aligned.m8n8.x2.shared.b16 {%0,%1}, [%2];\n"
                : "=r"(bb[0]), "=r"(bb[1]) : "r"(adb));
            asm volatile("mma.sync.aligned.m16n8k32.row.col.f32.e4m3.e4m3.f32 "
                "{%0,%1,%2,%3}, {%4,%5,%6,%7}, {%8,%9}, {%0,%1,%2,%3};\n"
                : "+f"(d0[0]), "+f"(d0[1]), "+f"(d0[2]), "+f"(d0[3])
                : "r"(a0[0]), "r"(a0[1]), "r"(a0[2]), "r"(a0[3]), "r"(bb[0]), "r"(bb[1]));
            asm volatile("mma.sync.aligned.m16n8k32.row.col.f32.e4m3.e4m3.f32 "
                "{%0,%1,%2,%3}, {%4,%5,%6,%7}, {%8,%9}, {%0,%1,%2,%3};\n"
                : "+f"(d1[0]), "+f"(d1[1]), "+f"(d1[2]), "+f"(d1[3])
                : "r"(a1[0]), "r"(a1[1]), "r"(a1[2]), "r"(a1[3]), "r"(bb[0]), "r"(bb[1]));
        }
        __syncthreads();
    }

    const int g = lane >> 2, tg = lane & 3;
    const int ncol = nBlk + warp * 8 + tg * 2;
#pragma unroll
    for (int mt = 0; mt < 2; mt++) {
        const float* dd = mt ? d1 : d0;
#pragma unroll
        for (int rr = 0; rr < 2; rr++) {
            int m = mt * 16 + rr * 8 + g;
#pragma unroll
            for (int cc = 0; cc < 2; cc++) {
                int col = ncol + cc;
                Z[(size_t)m * Gz + col] = dd[rr * 2 + cc] * UNSCALE;
            }
        }
    }
}

// ---------------- LSTM cell: z = z0 + z1 (+z2) + pre ----------------
__global__ void k_cell(const float* __restrict__ z0, const float* __restrict__ z1,
                       const float* __restrict__ z2, const float* __restrict__ pre,
                       float* __restrict__ c, uint8_t* __restrict__ h8,
                       bf16* __restrict__ hCopy) {
    int i = blockIdx.x * 256 + threadIdx.x;
    if (i >= Bz * Dz) return;
    int b = i >> 11, d = i & 2047;
    size_t o = (size_t)b * Gz + d;
    float ii = z0[o]          + z1[o]          + pre[o];
    float ff = z0[o + Dz]     + z1[o + Dz]     + pre[o + Dz];
    float gg = z0[o + 2 * Dz] + z1[o + 2 * Dz] + pre[o + 2 * Dz];
    float oo = z0[o + 3 * Dz] + z1[o + 3 * Dz] + pre[o + 3 * Dz];
    if (z2) {
        ii += z2[o];
        ff += z2[o + Dz];
        gg += z2[o + 2 * Dz];
        oo += z2[o + 3 * Dz];
    }
    float si = 1.f / (1.f + expf(-ii));
    float sf = 1.f / (1.f + expf(-ff));
    float so = 1.f / (1.f + expf(-oo));
    float tg = tanhf(gg);
    float cn = sf * c[i] + si * tg;
    c[i] = cn;
    float hv = so * tanhf(cn);
    h8[i] = __nv_cvt_float_to_fp8(hv * HSCALE, __NV_SATFINITE, __NV_E4M3);
    if (hCopy) hCopy[i] = __float2bfloat16(hv);
}

// ---------------- in-place log_softmax over V per (b,t) row ----------------
__global__ void k_lsm(float* __restrict__ out) {
    __shared__ float red[8];
    int r = blockIdx.x;
    float* p = out + (size_t)r * Vz;
    int tid = threadIdx.x;
    float m = -1e30f;
    for (int i = tid; i < Vz; i += 256) m = fmaxf(m, p[i]);
#pragma unroll
    for (int o = 16; o > 0; o >>= 1) m = fmaxf(m, __shfl_xor_sync(0xffffffffu, m, o));
    if ((tid & 31) == 0) red[tid >> 5] = m;
    __syncthreads();
    if (tid == 0) {
        float mm = red[0];
        for (int j = 1; j < 8; j++) mm = fmaxf(mm, red[j]);
        red[0] = mm;
    }
    __syncthreads();
    m = red[0];
    __syncthreads();
    float s = 0.f;
    for (int i = tid; i < Vz; i += 256) s += expf(p[i] - m);
#pragma unroll
    for (int o = 16; o > 0; o >>= 1) s += __shfl_xor_sync(0xffffffffu, s, o);
    if ((tid & 31) == 0) red[tid >> 5] = s;
    __syncthreads();
    if (tid == 0) {
        float ss = 0.f;
        for (int j = 0; j < 8; j++) ss += red[j];
        red[0] = ss;
    }
    __syncthreads();
    float lse = m + logf(red[0]);
    for (int i = tid; i < Vz; i += 256) p[i] -= lse;
}

// ---------------- host ----------------
extern "C" void kernel_launch(void* const* d_in, const int* in_sizes, int n_in,
                              void* d_out, int out_size) {
    const float* features = (const float*)d_in[0];
    const int*   caption  = (const int*)  d_in[1];
    const float* emb      = (const float*)d_in[2];
    const float* Wih_a    = (const float*)d_in[3];
    const float* Whh_a    = (const float*)d_in[4];
    const float* bih_a    = (const float*)d_in[5];
    const float* bhh_a    = (const float*)d_in[6];
    const float* Wih_l    = (const float*)d_in[7];
    const float* Whh_l    = (const float*)d_in[8];
    const float* bih_l    = (const float*)d_in[9];
    const float* bhh_l    = (const float*)d_in[10];
    const float* Wfc      = (const float*)d_in[17];
    const float* bfc      = (const float*)d_in[18];
    float* out = (float*)d_out;

    uint8_t *f8Ah, *f8Ahh, *f8Lh, *f8Lhh, *h8a, *h8l;
    bf16 *bAv, *bAe, *bLv, *bFC, *embsB, *vbarB, *vhatB, *hlAll;
    float *ca, *cl, *zz, *prevA, *preL, *preA;
    cudaGetSymbolAddress((void**)&f8Ah,  g_f8Ah);
    cudaGetSymbolAddress((void**)&f8Ahh, g_f8Ahh);
    cudaGetSymbolAddress((void**)&f8Lh,  g_f8Lh);
    cudaGetSymbolAddress((void**)&f8Lhh, g_f8Lhh);
    cudaGetSymbolAddress((void**)&h8a,   g_h8a);
    cudaGetSymbolAddress((void**)&h8l,   g_h8l);
    cudaGetSymbolAddress((void**)&bAv,   g_bAv);
    cudaGetSymbolAddress((void**)&bAe,   g_bAe);
    cudaGetSymbolAddress((void**)&bLv,   g_bLv);
    cudaGetSymbolAddress((void**)&bFC,   g_bFC);
    cudaGetSymbolAddress((void**)&embsB, g_embsB);
    cudaGetSymbolAddress((void**)&vbarB, g_vbarB);
    cudaGetSymbolAddress((void**)&vhatB, g_vhatB);
    cudaGetSymbolAddress((void**)&hlAll, g_hlAll);
    cudaGetSymbolAddress((void**)&ca,    g_caF);
    cudaGetSymbolAddress((void**)&cl,    g_clF);
    cudaGetSymbolAddress((void**)&zz,    g_zF);
    cudaGetSymbolAddress((void**)&prevA, g_prevAF);
    cudaGetSymbolAddress((void**)&preL,  g_preLF);
    cudaGetSymbolAddress((void**)&preA,  g_preAF);

    const size_t SLAB = (size_t)Bz * Gz;
    dim3 blk(128);

    // launch #1: feat + embs + state zero-init
    k_prep<<<(Bz * Tz * Dz + 255) / 256, 256>>>(features, emb, caption);

    // launch #2: all 8 weight conversions
    ConvJobs cj;
    const int cv4 = Gz * Dz / 4;
    const int cvFC = Vz * Dz / 4;
    cj.src[0] = Wih_a; cj.dst[0] = f8Ah;  cj.stride[0] = 3 * Dz; cj.off[0] = 0;      cj.total4[0] = cv4;  cj.isFp8[0] = 1;
    cj.src[1] = Whh_a; cj.dst[1] = f8Ahh; cj.stride[1] = Dz;     cj.off[1] = 0;      cj.total4[1] = cv4;  cj.isFp8[1] = 1;
    cj.src[2] = Wih_l; cj.dst[2] = f8Lh;  cj.stride[2] = 2 * Dz; cj.off[2] = 0;      cj.total4[2] = cv4;  cj.isFp8[2] = 1;
    cj.src[3] = Whh_l; cj.dst[3] = f8Lhh; cj.stride[3] = Dz;     cj.off[3] = 0;      cj.total4[3] = cv4;  cj.isFp8[3] = 1;
    cj.src[4] = Wih_a; cj.dst[4] = bAv;   cj.stride[4] = 3 * Dz; cj.off[4] = Dz;     cj.total4[4] = cv4;  cj.isFp8[4] = 0;
    cj.src[5] = Wih_a; cj.dst[5] = bAe;   cj.stride[5] = 3 * Dz; cj.off[5] = 2 * Dz; cj.total4[5] = cv4;  cj.isFp8[5] = 0;
    cj.src[6] = Wih_l; cj.dst[6] = bLv;   cj.stride[6] = 2 * Dz; cj.off[6] = Dz;     cj.total4[6] = cv4;  cj.isFp8[6] = 0;
    cj.src[7] = Wfc;   cj.dst[7] = bFC;   cj.stride[7] = Dz;     cj.off[7] = 0;      cj.total4[7] = cvFC; cj.isFp8[7] = 0;
    k_convall<<<dim3((cvFC + 255) / 256, 8), 256>>>(cj);

    // prevA / preL: tiny M=32 GEMMs
    k_gemm<<<dim3(Gz / 32, 1), blk>>>(vbarB, bAv, Dz, bih_a, bhh_a, prevA, Gz, Gz);
    k_gemm<<<dim3(Gz / 32, 1), blk>>>(vhatB, bLv, Dz, bih_l, bhh_l, preL, Gz, Gz);

    // preA: M=640 via big-M tiles (weight traffic /4 vs grid.y=20 variant)
    k_gemmBig<<<dim3(Gz / 32, 5), blk>>>(embsB, bAe, Dz, prevA, Gz, 1, nullptr,
                                         preA, Gz, Gz, 0);

    // recurrent loop (identical to R8/R13)
    for (int t = 0; t < Tz; t++) {
        JobSet8 jx;
        jx.A[0] = h8l;  jx.W[0] = f8Ah;   jx.Z[0] = zz;             jx.kOff[0] = 0;
        jx.A[1] = h8a;  jx.W[1] = f8Ahh;  jx.Z[1] = zz + SLAB;      jx.kOff[1] = 0;
        jx.A[2] = h8l;  jx.W[2] = f8Lhh;  jx.Z[2] = zz + 2 * SLAB;  jx.kOff[2] = 0;
        k_gemmJ8<<<dim3(Gz / 32, 3), blk>>>(jx, Dz);
        k_cell<<<(Bz * Dz + 255) / 256, 256>>>(zz, zz + SLAB, nullptr,
                                               preA + (size_t)t * SLAB,
                                               ca, h8a, nullptr);
        JobSet8 jy;
        jy.A[0] = h8a;  jy.W[0] = f8Lh;  jy.Z[0] = zz + 3 * SLAB;  jy.kOff[0] = 0;
        jy.A[1] = h8a;  jy.W[1] = f8Lh;  jy.Z[1] = zz + 4 * SLAB;  jy.kOff[1] = 1024;
        jy.A[2] = h8a;  jy.W[2] = f8Lh;  jy.Z[2] = zz + 4 * SLAB;  jy.kOff[2] = 1024;
        k_gemmJ8<<<dim3(Gz / 32, 2), blk>>>(jy, 1024);
        k_cell<<<(Bz * Dz + 255) / 256, 256>>>(zz + 2 * SLAB, zz + 3 * SLAB,
                                               zz + 4 * SLAB, preL,
                                               cl, h8l, hlAll + (size_t)t * Bz * Dz);
    }

    // batched logits via big-M tiles: rows r=t*32+b of hlAll @ Wfc^T + bfc -> out[b][t][:]
    k_gemmBig<<<dim3((Vz + 31) / 32, 5), blk>>>(hlAll, bFC, Dz, nullptr, 0, 0, bfc,
                                                out, Vz, Vz, 1);
    k_lsm<<<Bz * Tz, 256>>>(out);
}